// round 11
// baseline (speedup 1.0000x reference)
#include <cuda_runtime.h>

// Problem constants (fixed by the reference)
#define NB  32
#define NN  1024
#define NE  16384
#define NT  8
#define NDS 8
#define NH  32
#define PLANE (NN * NN)          // 1,048,576 cells per batch
#define CAP 256                  // worklist slots per (row,half) block; row degree
                                 // is ~Binomial(2E,1/N): mean 32, max ~52 -> 256 safe

// Scratch (no dynamic allocation). g_winner holds priority p = t+1 (>=1) via
// atomicMax over zero-initialized memory: idempotent across graph replays
// (fixed point on first call), 0 == untouched. No clear pass needed.
__device__ int g_winner[PLANE];      // 4 MB

// ---------------------------------------------------------------------------
// K1: priority mark. t in [0,2E): pass1 (src,dst) p=e+1, pass2 (dst,src)
// p=NE+e+1. atomicMax == reference's sequential last-write-wins .at[].set()
// (within a pass larger e wins; pass2 beats pass1). Result unused -> REDG.
// ---------------------------------------------------------------------------
__global__ void k_mark(const int* __restrict__ ei) {
    int t = blockIdx.x * blockDim.x + threadIdx.x;
    if (t >= 2 * NE) return;
    int e = t & (NE - 1);
    int s = __ldg(&ei[e]);
    int d = __ldg(&ei[NE + e]);
    int cell = (t < NE) ? (s * NN + d) : (d * NN + s);
    atomicMax(&g_winner[cell], t + 1);
}

// ---------------------------------------------------------------------------
// K2: fused winner-resolve + score + output stream.
// Block = (row, half of 16 batches). Thread tid owns columns [4tid, 4tid+4).
//  1. One LDG.128 fetches the thread's 4 winner priorities.
//  2. Touched columns are pushed to a shared worklist (slot index kept in
//     registers for the store phase).
//  3. Score tasks (slot x 16 batches) are distributed evenly over the block:
//     score = b2 + sum_j relu(dist*c_j + r*w1r_j + tpre[ty][j]) * w2_j
//     with c = w1[0]+w1[2], w1r = w1[1]-w1[2],
//     tpre[ty][j] = b1_j + emb(ty).w1[3:11,j]  (8 types x 32 j = 256 threads,
//     built once per block). Results land in shared s_tab[slot][16].
//  4. 16 batches of float4 evict-first stores, patched from s_tab via
//     register-predicated LDS. MLP work rides under the store stream.
// ---------------------------------------------------------------------------
__global__ void __launch_bounds__(256)
k_out(float* __restrict__ out,
      const float* __restrict__ xyz,
      const int*   __restrict__ ei,
      const int*   __restrict__ etype,
      const float* __restrict__ rest,
      const float* __restrict__ temb,
      const float* __restrict__ w1,
      const float* __restrict__ b1,
      const float* __restrict__ w2,
      const float* __restrict__ b2,
      const float* __restrict__ dflt) {
    __shared__ float2 s_tpw[NT * 33];        // (tpre[ty][j], w1r_j), 33-padded
    __shared__ float2 s_cw[NH];              // (c_j, w2_j)
    __shared__ float  s_tab[CAP * 16];       // scores [slot][brel]
    __shared__ int    s_eidx[CAP];           // slot -> edge
    __shared__ int    s_cnt;

    int tid  = threadIdx.x;
    int row  = blockIdx.x;
    int half = blockIdx.y;                   // 0/1 -> batches [16h, 16h+16)

    // Winner fetch (early, overlaps the setup below)
    int4 w = reinterpret_cast<const int4*>(g_winner + row * NN)[tid];

    // Per-block tables
    if (tid == 0) s_cnt = 0;
    if (tid < NH)
        s_cw[tid] = make_float2(__ldg(&w1[tid]) + __ldg(&w1[2 * NH + tid]),
                                __ldg(&w2[tid]));
    {
        int ty = tid >> 5, j = tid & 31;     // 8 x 32 == 256 threads
        float p = __ldg(&b1[j]);
#pragma unroll
        for (int k = 0; k < NDS; k++)
            p = fmaf(__ldg(&temb[ty * NDS + k]), __ldg(&w1[(3 + k) * NH + j]), p);
        s_tpw[ty * 33 + j] =
            make_float2(p, __ldg(&w1[1 * NH + j]) - __ldg(&w1[2 * NH + j]));
    }
    __syncthreads();

    // Worklist build: register slot per owned column
    int sl0 = -1, sl1 = -1, sl2 = -1, sl3 = -1;
    if (w.x > 0) { int p = atomicAdd(&s_cnt, 1); if (p < CAP) { s_eidx[p] = (w.x - 1) & (NE - 1); sl0 = p; } }
    if (w.y > 0) { int p = atomicAdd(&s_cnt, 1); if (p < CAP) { s_eidx[p] = (w.y - 1) & (NE - 1); sl1 = p; } }
    if (w.z > 0) { int p = atomicAdd(&s_cnt, 1); if (p < CAP) { s_eidx[p] = (w.z - 1) & (NE - 1); sl2 = p; } }
    if (w.w > 0) { int p = atomicAdd(&s_cnt, 1); if (p < CAP) { s_eidx[p] = (w.w - 1) & (NE - 1); sl3 = p; } }
    __syncthreads();

    // Score tasks: (slot, brel) pairs spread over 256 threads
    int nw = s_cnt < CAP ? s_cnt : CAP;
    float b2v = __ldg(b2);
    for (int t = tid; t < nw * 16; t += 256) {
        int wi   = t >> 4;
        int brel = t & 15;
        int b    = half * 16 + brel;
        int e    = s_eidx[wi];
        int s    = __ldg(&ei[e]);
        int d    = __ldg(&ei[NE + e]);
        int ty   = __ldg(&etype[e]);
        float r  = __ldg(&rest[e]);

        const float* pb = xyz + (size_t)b * NN * 3;
        float dx = __ldg(&pb[d * 3 + 0]) - __ldg(&pb[s * 3 + 0]);
        float dy = __ldg(&pb[d * 3 + 1]) - __ldg(&pb[s * 3 + 1]);
        float dz = __ldg(&pb[d * 3 + 2]) - __ldg(&pb[s * 3 + 2]);
        float dist = sqrtf(fmaf(dx, dx, fmaf(dy, dy, fmaf(dz, dz, 1e-12f))));

        float score = b2v;
        const float2* tpw = s_tpw + ty * 33;
#pragma unroll
        for (int j = 0; j < NH; j++) {
            float2 tw = tpw[j];
            float2 cw = s_cw[j];
            float pre = fmaf(r, tw.y, tw.x);
            float h   = fmaxf(fmaf(dist, cw.x, pre), 0.0f);
            score = fmaf(h, cw.y, score);
        }
        s_tab[wi * 16 + brel] = score;
    }
    __syncthreads();

    // Output stream: 16 batches of float4 stores with slot-predicated patches
    float dv = __ldg(dflt);
    float4* obase = reinterpret_cast<float4*>(out)
                  + (size_t)(half * 16) * (PLANE / 4)
                  + (size_t)row * (NN / 4) + tid;

#pragma unroll 8
    for (int b = 0; b < 16; b++) {
        float4 v = make_float4(dv, dv, dv, dv);
        if (sl0 >= 0) v.x = s_tab[sl0 * 16 + b];
        if (sl1 >= 0) v.y = s_tab[sl1 * 16 + b];
        if (sl2 >= 0) v.z = s_tab[sl2 * 16 + b];
        if (sl3 >= 0) v.w = s_tab[sl3 * 16 + b];
        __stcs(obase + (size_t)b * (PLANE / 4), v);
    }
}

// ---------------------------------------------------------------------------
// kernel_launch
// Input order: xyz, edge_index, edge_type, edge_rest_lengths, type_emb,
//              w1, b1, w2, b2, default_bias
// ---------------------------------------------------------------------------
extern "C" void kernel_launch(void* const* d_in, const int* in_sizes, int n_in,
                              void* d_out, int out_size) {
    const float* xyz   = (const float*)d_in[0];
    const int*   ei    = (const int*)  d_in[1];
    const int*   etype = (const int*)  d_in[2];
    const float* rest  = (const float*)d_in[3];
    const float* temb  = (const float*)d_in[4];
    const float* w1    = (const float*)d_in[5];
    const float* b1    = (const float*)d_in[6];
    const float* w2    = (const float*)d_in[7];
    const float* b2    = (const float*)d_in[8];
    const float* dflt  = (const float*)d_in[9];
    float* out = (float*)d_out;

    // K1: priority scatter (idempotent over zero-init / prior replays)
    k_mark<<<(2 * NE) / 256, 256>>>(ei);

    // K2: fused resolve + score + output, 2 blocks per row (16 batches each)
    {
        dim3 grid(NN, 2);
        k_out<<<grid, 256>>>(out, xyz, ei, etype, rest, temb,
                             w1, b1, w2, b2, dflt);
    }
}

// round 13
// speedup vs baseline: 1.4378x; 1.4378x over previous
#include <cuda_runtime.h>

// Problem constants (fixed by the reference)
#define NB  32
#define NN  1024
#define NE  16384
#define NT  8
#define NDS 8
#define NH  32
#define PLANE (NN * NN)          // 1,048,576 cells per batch

// Scratch (no dynamic allocation). g_winner holds priority p = t+1 (>=1) via
// atomicMax over zero-initialized memory: idempotent across graph replays
// (fixed point on first call), 0 == untouched. No clear pass needed.
__device__ int   g_winner[PLANE];      // 4 MB
__device__ float g_score[NB * NE];     // 2 MB: per (batch, edge) score

// ---------------------------------------------------------------------------
// K1: fused score + priority-mark.
// Block = (batch-group of 2, 256-edge chunk) -> 1024 blocks.
// bg==0 blocks also mark: priority t = e for (src,dst), NE+e for (dst,src);
// atomicMax(cell, t+1) == reference's sequential last-write-wins .at[].set().
//
// MLP folded:  feats.w1 = dist*c_j + [ r*w1r_j + (b1_j + emb(ty).w1e[:,j]) ]
// with c = w1[0]+w1[2], w1r = w1[1]-w1[2]; (b1 + emb.w1e) precomputed per
// block as tpre[8][32] (edge_type has only 8 values; 256 threads = 8x32).
//
// Both batches' xyz planes (contiguous, 24 KB) are staged into STATIC shared
// once (static total ~27.7 KB < 48 KB cap); the j-loop is fused across the
// 2 batches so one s_cw[j] LDS.64 feeds 2 independent FMA chains.
// ---------------------------------------------------------------------------
__global__ void __launch_bounds__(256)
k_score(const float* __restrict__ xyz,
        const int*   __restrict__ ei,
        const int*   __restrict__ etype,
        const float* __restrict__ rest,
        const float* __restrict__ temb,
        const float* __restrict__ w1,
        const float* __restrict__ b1,
        const float* __restrict__ w2,
        const float* __restrict__ b2) {
    __shared__ float  s_xyz[2 * NN * 3];     // 24 KB
    __shared__ float2 s_tpw[NT * 33];        // (tpre[ty][j], w1r_j), 33-padded
    __shared__ float2 s_cw[NH];              // (c_j, w2_j)
    __shared__ float  s_w1e[NDS * NH];
    __shared__ float  s_temb[NT * NDS];
    __shared__ float  s_b2;

    int tid   = threadIdx.x;
    int bg    = blockIdx.x >> 6;             // 0..15 (2 batches each)
    int chunk = blockIdx.x & 63;
    int e     = chunk * 256 + tid;           // 64*256 == NE

    // Stage 2 contiguous xyz planes (1536 float4)
    {
        const float4* src = reinterpret_cast<const float4*>(xyz + (size_t)bg * 2 * NN * 3);
        float4* dst = reinterpret_cast<float4*>(s_xyz);
#pragma unroll
        for (int i = 0; i < 6; i++)
            dst[tid + i * 256] = src[tid + i * 256];
    }
    for (int i = tid; i < NDS * NH; i += 256) s_w1e[i] = w1[3 * NH + i];
    for (int i = tid; i < NT * NDS; i += 256) s_temb[i] = temb[i];
    if (tid < NH)
        s_cw[tid] = make_float2(w1[tid] + w1[2 * NH + tid], w2[tid]);
    if (tid == 0) s_b2 = b2[0];
    __syncthreads();

    // Build tpre: thread tid -> (ty = tid>>5, j = tid&31)
    {
        int ty = tid >> 5, j = tid & 31;
        float p = b1[j];
#pragma unroll
        for (int k = 0; k < NDS; k++)
            p = fmaf(s_temb[ty * NDS + k], s_w1e[k * NH + j], p);
        s_tpw[ty * 33 + j] = make_float2(p, w1[1 * NH + j] - w1[2 * NH + j]);
    }
    __syncthreads();

    int s = ei[e];
    int d = ei[NE + e];

    if (bg == 0) {
        atomicMax(&g_winner[s * NN + d], e + 1);           // pass 1
        atomicMax(&g_winner[d * NN + s], NE + e + 1);      // pass 2 wins
    }

    float r  = rest[e];
    int   ty = etype[e];

    float pre[NH];
#pragma unroll
    for (int j = 0; j < NH; j++) {
        float2 tw = s_tpw[ty * 33 + j];
        pre[j] = fmaf(r, tw.y, tw.x);
    }

    // 2 distances (independent chains)
    float dist0, dist1;
    {
        const float* pl = s_xyz;
        float dx = pl[d * 3 + 0] - pl[s * 3 + 0];
        float dy = pl[d * 3 + 1] - pl[s * 3 + 1];
        float dz = pl[d * 3 + 2] - pl[s * 3 + 2];
        dist0 = sqrtf(fmaf(dx, dx, fmaf(dy, dy, fmaf(dz, dz, 1e-12f))));
    }
    {
        const float* pl = s_xyz + NN * 3;
        float dx = pl[d * 3 + 0] - pl[s * 3 + 0];
        float dy = pl[d * 3 + 1] - pl[s * 3 + 1];
        float dz = pl[d * 3 + 2] - pl[s * 3 + 2];
        dist1 = sqrtf(fmaf(dx, dx, fmaf(dy, dy, fmaf(dz, dz, 1e-12f))));
    }

    float sc0 = s_b2, sc1 = s_b2;
#pragma unroll
    for (int j = 0; j < NH; j++) {
        float2 cw = s_cw[j];
        float p = pre[j];
        float h0 = fmaxf(fmaf(dist0, cw.x, p), 0.0f);
        float h1 = fmaxf(fmaf(dist1, cw.x, p), 0.0f);
        sc0 = fmaf(h0, cw.y, sc0);
        sc1 = fmaf(h1, cw.y, sc1);
    }

    int b0 = bg * 2;
    g_score[(b0 + 0) * NE + e] = sc0;
    g_score[(b0 + 1) * NE + e] = sc1;
}

// ---------------------------------------------------------------------------
// K2: output (R10's proven version). Block = (row, half); thread tid owns
// columns [4tid, 4tid+4): one coalesced LDG.128 winner fetch, then 16 batches
// of float4 evict-first stores with register-predicated patches from the
// L2-resident score table.
// ---------------------------------------------------------------------------
__global__ void k_out(float* __restrict__ out, const float* __restrict__ dflt) {
    int tid  = threadIdx.x;
    int row  = blockIdx.x;
    int half = blockIdx.y;                   // 0/1 -> batches [16h, 16h+16)

    int4 w = reinterpret_cast<const int4*>(g_winner + row * NN)[tid];

    bool h0 = w.x > 0, h1 = w.y > 0, h2 = w.z > 0, h3 = w.w > 0;
    int  e0 = (w.x - 1) & (NE - 1);
    int  e1 = (w.y - 1) & (NE - 1);
    int  e2 = (w.z - 1) & (NE - 1);
    int  e3 = (w.w - 1) & (NE - 1);

    float dv = __ldg(dflt);
    float4* obase = reinterpret_cast<float4*>(out)
                  + (size_t)(half * 16) * (PLANE / 4)
                  + (size_t)row * (NN / 4) + tid;
    const float* scbase = g_score + half * 16 * NE;

#pragma unroll 8
    for (int b = 0; b < 16; b++) {
        float4 v = make_float4(dv, dv, dv, dv);
        const float* sc = scbase + b * NE;
        if (h0) v.x = sc[e0];
        if (h1) v.y = sc[e1];
        if (h2) v.z = sc[e2];
        if (h3) v.w = sc[e3];
        __stcs(obase + (size_t)b * (PLANE / 4), v);
    }
}

// ---------------------------------------------------------------------------
// kernel_launch
// Input order: xyz, edge_index, edge_type, edge_rest_lengths, type_emb,
//              w1, b1, w2, b2, default_bias
// ---------------------------------------------------------------------------
extern "C" void kernel_launch(void* const* d_in, const int* in_sizes, int n_in,
                              void* d_out, int out_size) {
    const float* xyz   = (const float*)d_in[0];
    const int*   ei    = (const int*)  d_in[1];
    const int*   etype = (const int*)  d_in[2];
    const float* rest  = (const float*)d_in[3];
    const float* temb  = (const float*)d_in[4];
    const float* w1    = (const float*)d_in[5];
    const float* b1    = (const float*)d_in[6];
    const float* w2    = (const float*)d_in[7];
    const float* b2    = (const float*)d_in[8];
    const float* dflt  = (const float*)d_in[9];
    float* out = (float*)d_out;

    // K1: fused score + mark (16 batch-groups x 64 edge-chunks = 1024 blocks)
    k_score<<<16 * 64, 256>>>(xyz, ei, etype, rest, temb, w1, b1, w2, b2);

    // K2: output, 2 blocks per row (16 batches each)
    {
        dim3 grid(NN, 2);
        k_out<<<grid, 256>>>(out, dflt);
    }
}